// round 1
// baseline (speedup 1.0000x reference)
#include <cuda_runtime.h>

// Problem constants
#define BB 2
#define SS 2048
#define DD 1024
#define HH 16
#define DH 64

// Scratch (device globals; no allocation allowed)
__device__ float g_q[BB * HH * SS * DH];    // [b,h,s,dh]
__device__ float g_k[BB * HH * SS * DH];
__device__ float g_v[BB * HH * SS * DH];
__device__ float g_ctx[BB * SS * DD];       // [b,s,D]

// ---------------------------------------------------------------------------
// Tiled SGEMM: C[m,n] = sum_k A[m,k] * W[n,k]  (i.e. A @ W^T), fp32.
// BM=BN=64, BK=16, 256 threads, 4x4 micro-tile per thread.
// MODE 0: C row-major [M,N], + bias
// MODE 1: scatter into [b,h,s,dh] head layout (for QKV projections)
// ---------------------------------------------------------------------------
template <int MODE>
__global__ __launch_bounds__(256) void gemm_nt(
    const float* __restrict__ A, const float* __restrict__ W,
    const float* __restrict__ bias, float* __restrict__ C,
    int M, int N, int K)
{
    __shared__ float As[16][64];  // transposed: As[k][m]
    __shared__ float Bs[16][64];  // transposed: Bs[k][n]

    const int tid = threadIdx.x;
    const int tx = tid & 15;      // n direction (16)
    const int ty = tid >> 4;      // m direction (16)
    const int row0 = blockIdx.y * 64;
    const int col0 = blockIdx.x * 64;

    float acc[4][4] = {};

    const int lm = tid >> 2;        // 0..63 : row within tile
    const int lk = (tid & 3) * 4;   // 0,4,8,12 : k offset
    const float* Aptr = A + (long)(row0 + lm) * K + lk;
    const float* Wptr = W + (long)(col0 + lm) * K + lk;

    for (int k0 = 0; k0 < K; k0 += 16) {
        float4 av = *(const float4*)(Aptr + k0);
        float4 bv = *(const float4*)(Wptr + k0);
        As[lk + 0][lm] = av.x; As[lk + 1][lm] = av.y;
        As[lk + 2][lm] = av.z; As[lk + 3][lm] = av.w;
        Bs[lk + 0][lm] = bv.x; Bs[lk + 1][lm] = bv.y;
        Bs[lk + 2][lm] = bv.z; Bs[lk + 3][lm] = bv.w;
        __syncthreads();

        #pragma unroll
        for (int k = 0; k < 16; k++) {
            float4 a = *(const float4*)&As[k][ty * 4];
            float4 b = *(const float4*)&Bs[k][tx * 4];
            float ar[4] = {a.x, a.y, a.z, a.w};
            float br[4] = {b.x, b.y, b.z, b.w};
            #pragma unroll
            for (int i = 0; i < 4; i++)
                #pragma unroll
                for (int j = 0; j < 4; j++)
                    acc[i][j] = fmaf(ar[i], br[j], acc[i][j]);
        }
        __syncthreads();
    }

    if (MODE == 0) {
        #pragma unroll
        for (int i = 0; i < 4; i++) {
            int m = row0 + ty * 4 + i;
            #pragma unroll
            for (int j = 0; j < 4; j++) {
                int n = col0 + tx * 4 + j;
                C[(long)m * N + n] = acc[i][j] + bias[n];
            }
        }
    } else {
        // scatter to [b,h,s,dh]: m = b*SS + s ; n = h*DH + dh
        #pragma unroll
        for (int i = 0; i < 4; i++) {
            int m = row0 + ty * 4 + i;
            int b = m >> 11;            // /SS
            int s = m & (SS - 1);
            #pragma unroll
            for (int j = 0; j < 4; j++) {
                int n = col0 + tx * 4 + j;
                int h = n >> 6;         // /DH
                int dh = n & (DH - 1);
                C[(((long)(b * HH + h)) * SS + s) * DH + dh] = acc[i][j];
            }
        }
    }
}

// ---------------------------------------------------------------------------
// Flash attention (causal), fp32. BLOCK_M = BLOCK_N = 64, DH = 64.
// 256 threads, 4x4 micro-tile (tx over key/headdim cols, ty over query rows).
// Online softmax in exp2 domain. P tile reuses the K smem buffer.
// Smem rows padded to 68 floats (float4-aligned, conflict-mitigating).
// ---------------------------------------------------------------------------
#define PAD 68
#define FLASH_SMEM (3 * 64 * PAD * 4)

__global__ __launch_bounds__(256) void flash_kernel(
    const float* __restrict__ Q, const float* __restrict__ K,
    const float* __restrict__ V, float* __restrict__ ctx)
{
    extern __shared__ float sm[];
    float* Qs = sm;                 // [d][s]  (transposed)
    float* Ks = sm + 64 * PAD;      // [d][s]  (transposed); later reused as P[n][m]
    float* Vs = sm + 2 * 64 * PAD;  // [s][d]

    const int tid = threadIdx.x;
    const int tx = tid & 15;
    const int ty = tid >> 4;
    const int bh = blockIdx.y;      // b*HH + h
    const int qt = blockIdx.x;      // query tile

    const float* Qb = Q + ((long)bh * SS + qt * 64) * DH;

    float acc[4][4] = {};
    float Mrow[4], Lrow[4];
    #pragma unroll
    for (int i = 0; i < 4; i++) { Mrow[i] = -1e30f; Lrow[i] = 0.f; }

    // load Q tile transposed: Qs[d][s]
    for (int idx = tid; idx < 64 * 64; idx += 256) {
        int r = idx >> 6, c = idx & 63;
        Qs[c * PAD + r] = Qb[r * 64 + c];
    }

    const float SCL = 0.18033688011112043f;  // (1/sqrt(64)) * log2(e)

    for (int kt = 0; kt <= qt; kt++) {
        const float* Kb = K + ((long)bh * SS + kt * 64) * DH;
        const float* Vb = V + ((long)bh * SS + kt * 64) * DH;

        __syncthreads();  // protect previous iteration's P/V reads (and Q load on iter 0)
        for (int idx = tid; idx < 64 * 64; idx += 256) {
            int r = idx >> 6, c = idx & 63;
            Ks[c * PAD + r] = Kb[r * 64 + c];
            Vs[r * PAD + c] = Vb[r * 64 + c];
        }
        __syncthreads();

        // S = Q @ K^T  (contract over d)
        float s[4][4] = {};
        #pragma unroll 8
        for (int kk = 0; kk < 64; kk++) {
            float4 a = *(const float4*)&Qs[kk * PAD + ty * 4];
            float4 b = *(const float4*)&Ks[kk * PAD + tx * 4];
            float ar[4] = {a.x, a.y, a.z, a.w};
            float br[4] = {b.x, b.y, b.z, b.w};
            #pragma unroll
            for (int i = 0; i < 4; i++)
                #pragma unroll
                for (int j = 0; j < 4; j++)
                    s[i][j] = fmaf(ar[i], br[j], s[i][j]);
        }

        const bool diag = (kt == qt);
        float t[4][4];
        #pragma unroll
        for (int i = 0; i < 4; i++) {
            int qi = ty * 4 + i;
            #pragma unroll
            for (int j = 0; j < 4; j++) {
                int kj = tx * 4 + j;
                float tv = s[i][j] * SCL;
                if (diag && kj > qi) tv = -1e30f;
                t[i][j] = tv;
            }
        }

        // row max (over 16 tx lanes) + online softmax update
        float p[4][4];
        float rsum[4];
        #pragma unroll
        for (int i = 0; i < 4; i++) {
            float rm = fmaxf(fmaxf(t[i][0], t[i][1]), fmaxf(t[i][2], t[i][3]));
            #pragma unroll
            for (int o = 8; o > 0; o >>= 1)
                rm = fmaxf(rm, __shfl_xor_sync(0xffffffffu, rm, o));
            float Mnew = fmaxf(Mrow[i], rm);
            float corr = exp2f(Mrow[i] - Mnew);
            float rs = 0.f;
            #pragma unroll
            for (int j = 0; j < 4; j++) {
                float pv = exp2f(t[i][j] - Mnew);
                p[i][j] = pv;
                rs += pv;
            }
            #pragma unroll
            for (int o = 8; o > 0; o >>= 1)
                rs += __shfl_xor_sync(0xffffffffu, rs, o);
            Lrow[i] = Lrow[i] * corr + rs;
            Mrow[i] = Mnew;
            #pragma unroll
            for (int j = 0; j < 4; j++) acc[i][j] *= corr;
            rsum[i] = rs; (void)rsum;
        }

        __syncthreads();  // everyone done reading Ks before P overwrite
        // write P transposed into Ks buffer: P[n][m]
        #pragma unroll
        for (int j = 0; j < 4; j++)
            #pragma unroll
            for (int i = 0; i < 4; i++)
                Ks[(tx * 4 + j) * PAD + ty * 4 + i] = p[i][j];
        __syncthreads();

        // O += P @ V  (contract over n)
        #pragma unroll 8
        for (int n = 0; n < 64; n++) {
            float4 a = *(const float4*)&Ks[n * PAD + ty * 4];
            float4 b = *(const float4*)&Vs[n * PAD + tx * 4];
            float ar[4] = {a.x, a.y, a.z, a.w};
            float br[4] = {b.x, b.y, b.z, b.w};
            #pragma unroll
            for (int i = 0; i < 4; i++)
                #pragma unroll
                for (int j = 0; j < 4; j++)
                    acc[i][j] = fmaf(ar[i], br[j], acc[i][j]);
        }
    }

    // write ctx[b, s, h*DH + d]
    const int b = bh >> 4;
    const int h = bh & 15;
    #pragma unroll
    for (int i = 0; i < 4; i++) {
        int srow = qt * 64 + ty * 4 + i;
        float inv = 1.0f / Lrow[i];
        #pragma unroll
        for (int j = 0; j < 4; j++) {
            int d = tx * 4 + j;
            g_ctx[((long)(b * SS + srow)) * DD + h * DH + d] = acc[i][j] * inv;
        }
    }
}

// ---------------------------------------------------------------------------
extern "C" void kernel_launch(void* const* d_in, const int* in_sizes, int n_in,
                              void* d_out, int out_size)
{
    (void)in_sizes; (void)n_in; (void)out_size;
    const float* x  = (const float*)d_in[0];
    const float* Wq = (const float*)d_in[1];
    const float* Wk = (const float*)d_in[2];
    const float* Wv = (const float*)d_in[3];
    const float* Wo = (const float*)d_in[4];
    const float* bo = (const float*)d_in[5];
    float* out = (float*)d_out;

    float *qp, *kp, *vp, *cp;
    cudaGetSymbolAddress((void**)&qp, g_q);
    cudaGetSymbolAddress((void**)&kp, g_k);
    cudaGetSymbolAddress((void**)&vp, g_v);
    cudaGetSymbolAddress((void**)&cp, g_ctx);

    const int M = BB * SS;   // 4096
    const int N = DD;        // 1024
    const int Kk = DD;       // 1024

    dim3 gblk(256);
    dim3 ggrid(N / 64, M / 64);  // (16, 64)

    // QKV projections (scatter to head layout)
    gemm_nt<1><<<ggrid, gblk>>>(x, Wq, nullptr, qp, M, N, Kk);
    gemm_nt<1><<<ggrid, gblk>>>(x, Wk, nullptr, kp, M, N, Kk);
    gemm_nt<1><<<ggrid, gblk>>>(x, Wv, nullptr, vp, M, N, Kk);

    // Flash attention (causal)
    cudaFuncSetAttribute(flash_kernel,
                         cudaFuncAttributeMaxDynamicSharedMemorySize, FLASH_SMEM);
    dim3 fgrid(SS / 64, BB * HH);  // (32, 32)
    flash_kernel<<<fgrid, gblk, FLASH_SMEM>>>(qp, kp, vp, cp);

    // Output projection + bias
    gemm_nt<0><<<ggrid, gblk>>>(cp, Wo, bo, out, M, N, Kk);
}

// round 8
// speedup vs baseline: 1.6909x; 1.6909x over previous
#include <cuda_runtime.h>
#include <cuda_bf16.h>
#include <cstdint>

// Problem constants
#define BB 2
#define SS 2048
#define DD 1024
#define HH 16
#define DH 64
#define MM (BB * SS)   // 4096

// ---------------------------------------------------------------------------
// Scratch (device globals; no allocation allowed)
// ---------------------------------------------------------------------------
__device__ float g_q[BB * HH * SS * DH];    // [b,h,s,dh]
__device__ float g_k[BB * HH * SS * DH];
__device__ float g_v[BB * HH * SS * DH];
__device__ float g_ctx[BB * SS * DD];       // [b,s,D]

__device__ __nv_bfloat16 g_xh[MM * DD], g_xl[MM * DD];       // split x
__device__ __nv_bfloat16 g_wh[4][DD * DD], g_wl[4][DD * DD]; // split Wq,Wk,Wv,Wo
__device__ __nv_bfloat16 g_ch[MM * DD], g_cl[MM * DD];       // split ctx

// ---------------------------------------------------------------------------
// Baseline-PTX helpers (no sm_103a-specific instructions!)
// ---------------------------------------------------------------------------
__device__ __forceinline__ uint32_t smem_u32(const void* p) {
    uint32_t a;
    asm("{ .reg .u64 t; cvta.to.shared.u64 t, %1; cvt.u32.u64 %0, t; }"
        : "=r"(a) : "l"(p));
    return a;
}

__device__ __forceinline__ void cp16(uint32_t saddr, const void* g) {
    asm volatile("cp.async.cg.shared.global [%0], [%1], 16;"
                 :: "r"(saddr), "l"(g) : "memory");
}
#define CP_COMMIT() asm volatile("cp.async.commit_group;" ::: "memory")
#define CP_WAIT(n)  asm volatile("cp.async.wait_group %0;" :: "n"(n) : "memory")

__device__ __forceinline__ void ldsm4(uint32_t* r, uint32_t addr) {
    asm volatile("ldmatrix.sync.aligned.m8n8.x4.shared.b16 {%0,%1,%2,%3}, [%4];"
                 : "=r"(r[0]), "=r"(r[1]), "=r"(r[2]), "=r"(r[3]) : "r"(addr));
}

__device__ __forceinline__ void mma_bf16(float* d, const uint32_t* a, const uint32_t* b) {
    asm volatile(
        "mma.sync.aligned.m16n8k16.row.col.f32.bf16.bf16.f32 "
        "{%0,%1,%2,%3}, {%4,%5,%6,%7}, {%8,%9}, {%0,%1,%2,%3};"
        : "+f"(d[0]), "+f"(d[1]), "+f"(d[2]), "+f"(d[3])
        : "r"(a[0]), "r"(a[1]), "r"(a[2]), "r"(a[3]), "r"(b[0]), "r"(b[1]));
}

// ---------------------------------------------------------------------------
// fp32 -> bf16 hi/lo split conversion
// ---------------------------------------------------------------------------
__global__ __launch_bounds__(256) void convert_split(
    const float* __restrict__ in, __nv_bfloat16* __restrict__ hi,
    __nv_bfloat16* __restrict__ lo, int n4)
{
    int i = blockIdx.x * blockDim.x + threadIdx.x;
    if (i >= n4) return;
    float4 v = ((const float4*)in)[i];
    __nv_bfloat16 h0 = __float2bfloat16(v.x);
    __nv_bfloat16 h1 = __float2bfloat16(v.y);
    __nv_bfloat16 h2 = __float2bfloat16(v.z);
    __nv_bfloat16 h3 = __float2bfloat16(v.w);
    __nv_bfloat16 l0 = __float2bfloat16(v.x - __bfloat162float(h0));
    __nv_bfloat16 l1 = __float2bfloat16(v.y - __bfloat162float(h1));
    __nv_bfloat16 l2 = __float2bfloat16(v.z - __bfloat162float(h2));
    __nv_bfloat16 l3 = __float2bfloat16(v.w - __bfloat162float(h3));
    ((__nv_bfloat162*)hi)[2 * i]     = __nv_bfloat162(h0, h1);
    ((__nv_bfloat162*)hi)[2 * i + 1] = __nv_bfloat162(h2, h3);
    ((__nv_bfloat162*)lo)[2 * i]     = __nv_bfloat162(l0, l1);
    ((__nv_bfloat162*)lo)[2 * i + 1] = __nv_bfloat162(l2, l3);
}

// ---------------------------------------------------------------------------
// HMMA split-bf16 GEMM: C[m,n] = sum_k A[m,k] * W[n,k]  (fp32 accum)
// CTA tile 128x128, BK=64, 8 warps (4m x 2n), warp tile 32x64.
// cp.async double-buffered smem, padded rows (72 halves) for conflict-free
// ldmatrix. C = Ah*Wh + Ah*Wl + Al*Wh.
// MODE 0: C row-major [M,N] + bias.  MODE 1: scatter to [b,h,s,dh].
// ---------------------------------------------------------------------------
#define BKC 64
#define APAD 72                       // halves per smem row
#define ROWB (APAD * 2)               // 144 bytes per row
#define ABYTES (128 * ROWB)           // 18432 per array
#define STAGEB (4 * ABYTES)           // Ah,Al,Bh,Bl per stage
#define GEMM_SMEM (2 * STAGEB)        // 147456

template <int MODE>
__global__ __launch_bounds__(256) void gemm_mma(
    const __nv_bfloat16* __restrict__ Ah, const __nv_bfloat16* __restrict__ Al,
    const __nv_bfloat16* __restrict__ Wh, const __nv_bfloat16* __restrict__ Wl,
    const float* __restrict__ bias, float* __restrict__ C)
{
    extern __shared__ char smem[];
    const uint32_t sb = smem_u32(smem);
    const int tid = threadIdx.x;
    const int wid = tid >> 5;
    const int lane = tid & 31;
    const int wm = wid & 3;       // m warp 0..3
    const int wn = wid >> 2;      // n warp 0..1
    const int row0 = blockIdx.y * 128;
    const int col0 = blockIdx.x * 128;

    const __nv_bfloat16* gp[4] = {Ah, Al, Wh, Wl};
    const int rb[4] = {row0, row0, col0, col0};

    float acc[2][8][4] = {};

    // --- async load of chunk `c` into stage `s` ---
    auto issue = [&](int c, int s) {
        const int k0 = c * BKC;
        #pragma unroll
        for (int a = 0; a < 4; a++) {
            #pragma unroll
            for (int j = 0; j < 4; j++) {
                int idx = j * 256 + tid;           // 0..1023
                int row = idx >> 3;                // 0..127
                int c16 = idx & 7;                 // 16B chunk within 128B row
                uint32_t so = sb + s * STAGEB + a * ABYTES + row * ROWB + c16 * 16;
                const void* g = gp[a] + (size_t)(rb[a] + row) * DD + k0 + c16 * 8;
                cp16(so, g);
            }
        }
        CP_COMMIT();
    };

    issue(0, 0);

    for (int c = 0; c < 16; c++) {
        const int s = c & 1;
        if (c < 15) issue(c + 1, s ^ 1);
        if (c < 15) { CP_WAIT(1); } else { CP_WAIT(0); }
        __syncthreads();

        const uint32_t st = sb + s * STAGEB;
        #pragma unroll
        for (int ks = 0; ks < 4; ks++) {
            const int lr = lane & 15;
            const int lc = ks * 16 + (lane >> 4) * 8;

            uint32_t ah[2][4], al[2][4], bh[8][2], bl[8][2];
            #pragma unroll
            for (int mi = 0; mi < 2; mi++) {
                uint32_t base = st + (wm * 32 + mi * 16 + lr) * ROWB + lc * 2;
                ldsm4(ah[mi], base);
                ldsm4(al[mi], base + ABYTES);
            }
            #pragma unroll
            for (int nt = 0; nt < 4; nt++) {
                uint32_t base = st + 2 * ABYTES + (wn * 64 + nt * 16 + lr) * ROWB + lc * 2;
                uint32_t r[4], q[4];
                ldsm4(r, base);
                ldsm4(q, base + ABYTES);
                bh[nt * 2][0] = r[0]; bh[nt * 2][1] = r[2];
                bh[nt * 2 + 1][0] = r[1]; bh[nt * 2 + 1][1] = r[3];
                bl[nt * 2][0] = q[0]; bl[nt * 2][1] = q[2];
                bl[nt * 2 + 1][0] = q[1]; bl[nt * 2 + 1][1] = q[3];
            }
            #pragma unroll
            for (int mi = 0; mi < 2; mi++)
                #pragma unroll
                for (int nj = 0; nj < 8; nj++) {
                    mma_bf16(acc[mi][nj], ah[mi], bh[nj]);
                    mma_bf16(acc[mi][nj], ah[mi], bl[nj]);
                    mma_bf16(acc[mi][nj], al[mi], bh[nj]);
                }
        }
        __syncthreads();
    }

    // --- epilogue ---
    const int qr = lane >> 2;          // 0..7
    const int qc = (lane & 3) * 2;     // 0,2,4,6

    #pragma unroll
    for (int mi = 0; mi < 2; mi++) {
        const int mbase = row0 + wm * 32 + mi * 16 + qr;
        #pragma unroll
        for (int nj = 0; nj < 8; nj++) {
            const int n = col0 + wn * 64 + nj * 8 + qc;
            if (MODE == 0) {
                float2 b0 = *(const float2*)(bias + n);
                float2 o0 = { acc[mi][nj][0] + b0.x, acc[mi][nj][1] + b0.y };
                float2 o1 = { acc[mi][nj][2] + b0.x, acc[mi][nj][3] + b0.y };
                *(float2*)(C + (size_t)mbase * DD + n) = o0;
                *(float2*)(C + (size_t)(mbase + 8) * DD + n) = o1;
            } else {
                const int h = n >> 6;
                const int dh = n & (DH - 1);
                const int b0_ = mbase >> 11;
                const int s0 = mbase & (SS - 1);
                float2 o0 = { acc[mi][nj][0], acc[mi][nj][1] };
                float2 o1 = { acc[mi][nj][2], acc[mi][nj][3] };
                *(float2*)(C + (((size_t)(b0_ * HH + h)) * SS + s0) * DH + dh) = o0;
                *(float2*)(C + (((size_t)(b0_ * HH + h)) * SS + s0 + 8) * DH + dh) = o1;
            }
        }
    }
}

// ---------------------------------------------------------------------------
// Flash attention (causal), fp32 SIMT (R1 version)
// ---------------------------------------------------------------------------
#define PAD 68
#define FLASH_SMEM (3 * 64 * PAD * 4)

__global__ __launch_bounds__(256) void flash_kernel(
    const float* __restrict__ Q, const float* __restrict__ K,
    const float* __restrict__ V, float* __restrict__ ctx)
{
    extern __shared__ float sm[];
    float* Qs = sm;
    float* Ks = sm + 64 * PAD;
    float* Vs = sm + 2 * 64 * PAD;

    const int tid = threadIdx.x;
    const int tx = tid & 15;
    const int ty = tid >> 4;
    const int bh = blockIdx.y;
    const int qt = blockIdx.x;

    const float* Qb = Q + ((long)bh * SS + qt * 64) * DH;

    float acc[4][4] = {};
    float Mrow[4], Lrow[4];
    #pragma unroll
    for (int i = 0; i < 4; i++) { Mrow[i] = -1e30f; Lrow[i] = 0.f; }

    for (int idx = tid; idx < 64 * 64; idx += 256) {
        int r = idx >> 6, c = idx & 63;
        Qs[c * PAD + r] = Qb[r * 64 + c];
    }

    const float SCL = 0.18033688011112043f;  // (1/sqrt(64)) * log2(e)

    for (int kt = 0; kt <= qt; kt++) {
        const float* Kb = K + ((long)bh * SS + kt * 64) * DH;
        const float* Vb = V + ((long)bh * SS + kt * 64) * DH;

        __syncthreads();
        for (int idx = tid; idx < 64 * 64; idx += 256) {
            int r = idx >> 6, c = idx & 63;
            Ks[c * PAD + r] = Kb[r * 64 + c];
            Vs[r * PAD + c] = Vb[r * 64 + c];
        }
        __syncthreads();

        float s[4][4] = {};
        #pragma unroll 8
        for (int kk = 0; kk < 64; kk++) {
            float4 a = *(const float4*)&Qs[kk * PAD + ty * 4];
            float4 b = *(const float4*)&Ks[kk * PAD + tx * 4];
            float ar[4] = {a.x, a.y, a.z, a.w};
            float br[4] = {b.x, b.y, b.z, b.w};
            #pragma unroll
            for (int i = 0; i < 4; i++)
                #pragma unroll
                for (int j = 0; j < 4; j++)
                    s[i][j] = fmaf(ar[i], br[j], s[i][j]);
        }

        const bool diag = (kt == qt);
        float t[4][4];
        #pragma unroll
        for (int i = 0; i < 4; i++) {
            int qi = ty * 4 + i;
            #pragma unroll
            for (int j = 0; j < 4; j++) {
                int kj = tx * 4 + j;
                float tv = s[i][j] * SCL;
                if (diag && kj > qi) tv = -1e30f;
                t[i][j] = tv;
            }
        }

        float p[4][4];
        #pragma unroll
        for (int i = 0; i < 4; i++) {
            float rm = fmaxf(fmaxf(t[i][0], t[i][1]), fmaxf(t[i][2], t[i][3]));
            #pragma unroll
            for (int o = 8; o > 0; o >>= 1)
                rm = fmaxf(rm, __shfl_xor_sync(0xffffffffu, rm, o));
            float Mnew = fmaxf(Mrow[i], rm);
            float corr = exp2f(Mrow[i] - Mnew);
            float rs = 0.f;
            #pragma unroll
            for (int j = 0; j < 4; j++) {
                float pv = exp2f(t[i][j] - Mnew);
                p[i][j] = pv;
                rs += pv;
            }
            #pragma unroll
            for (int o = 8; o > 0; o >>= 1)
                rs += __shfl_xor_sync(0xffffffffu, rs, o);
            Lrow[i] = Lrow[i] * corr + rs;
            Mrow[i] = Mnew;
            #pragma unroll
            for (int j = 0; j < 4; j++) acc[i][j] *= corr;
        }

        __syncthreads();
        #pragma unroll
        for (int j = 0; j < 4; j++)
            #pragma unroll
            for (int i = 0; i < 4; i++)
                Ks[(tx * 4 + j) * PAD + ty * 4 + i] = p[i][j];
        __syncthreads();

        #pragma unroll 8
        for (int n = 0; n < 64; n++) {
            float4 a = *(const float4*)&Ks[n * PAD + ty * 4];
            float4 b = *(const float4*)&Vs[n * PAD + tx * 4];
            float ar[4] = {a.x, a.y, a.z, a.w};
            float br[4] = {b.x, b.y, b.z, b.w};
            #pragma unroll
            for (int i = 0; i < 4; i++)
                #pragma unroll
                for (int j = 0; j < 4; j++)
                    acc[i][j] = fmaf(ar[i], br[j], acc[i][j]);
        }
    }

    const int b = bh >> 4;
    const int h = bh & 15;
    #pragma unroll
    for (int i = 0; i < 4; i++) {
        int srow = qt * 64 + ty * 4 + i;
        float inv = 1.0f / Lrow[i];
        #pragma unroll
        for (int j = 0; j < 4; j++) {
            int d = tx * 4 + j;
            ctx[((long)(b * SS + srow)) * DD + h * DH + d] = acc[i][j] * inv;
        }
    }
}

// ---------------------------------------------------------------------------
extern "C" void kernel_launch(void* const* d_in, const int* in_sizes, int n_in,
                              void* d_out, int out_size)
{
    (void)in_sizes; (void)n_in; (void)out_size;
    const float* x  = (const float*)d_in[0];
    const float* Wq = (const float*)d_in[1];
    const float* Wk = (const float*)d_in[2];
    const float* Wv = (const float*)d_in[3];
    const float* Wo = (const float*)d_in[4];
    const float* bo = (const float*)d_in[5];
    float* out = (float*)d_out;

    float *qp, *kp, *vp, *cp;
    cudaGetSymbolAddress((void**)&qp, g_q);
    cudaGetSymbolAddress((void**)&kp, g_k);
    cudaGetSymbolAddress((void**)&vp, g_v);
    cudaGetSymbolAddress((void**)&cp, g_ctx);
    __nv_bfloat16 *xh, *xl, *wh, *wl, *ch, *cl;
    cudaGetSymbolAddress((void**)&xh, g_xh);
    cudaGetSymbolAddress((void**)&xl, g_xl);
    cudaGetSymbolAddress((void**)&wh, g_wh);
    cudaGetSymbolAddress((void**)&wl, g_wl);
    cudaGetSymbolAddress((void**)&ch, g_ch);
    cudaGetSymbolAddress((void**)&cl, g_cl);

    // Split conversions
    convert_split<<<(MM * DD / 4) / 256, 256>>>(x, xh, xl, MM * DD / 4);
    const float* Ws[4] = {Wq, Wk, Wv, Wo};
    for (int i = 0; i < 4; i++)
        convert_split<<<(DD * DD / 4) / 256, 256>>>(
            Ws[i], wh + (size_t)i * DD * DD, wl + (size_t)i * DD * DD, DD * DD / 4);

    // HMMA GEMMs: QKV projections (scatter to head layout)
    cudaFuncSetAttribute(gemm_mma<0>, cudaFuncAttributeMaxDynamicSharedMemorySize, GEMM_SMEM);
    cudaFuncSetAttribute(gemm_mma<1>, cudaFuncAttributeMaxDynamicSharedMemorySize, GEMM_SMEM);
    dim3 ggrid(DD / 128, MM / 128);   // (8, 32)
    gemm_mma<1><<<ggrid, 256, GEMM_SMEM>>>(xh, xl, wh, wl, nullptr, qp);
    gemm_mma<1><<<ggrid, 256, GEMM_SMEM>>>(xh, xl, wh + (size_t)DD * DD, wl + (size_t)DD * DD, nullptr, kp);
    gemm_mma<1><<<ggrid, 256, GEMM_SMEM>>>(xh, xl, wh + 2 * (size_t)DD * DD, wl + 2 * (size_t)DD * DD, nullptr, vp);

    // Flash attention (causal)
    cudaFuncSetAttribute(flash_kernel, cudaFuncAttributeMaxDynamicSharedMemorySize, FLASH_SMEM);
    dim3 fgrid(SS / 64, BB * HH);
    flash_kernel<<<fgrid, 256, FLASH_SMEM>>>(qp, kp, vp, cp);

    // Split ctx, then output projection + bias
    convert_split<<<(MM * DD / 4) / 256, 256>>>(cp, ch, cl, MM * DD / 4);
    gemm_mma<0><<<ggrid, 256, GEMM_SMEM>>>(ch, cl, wh + 3 * (size_t)DD * DD, wl + 3 * (size_t)DD * DD, bo, out);
}